// round 11
// baseline (speedup 1.0000x reference)
#include <cuda_runtime.h>

// N = 2^26 FFT of REAL fp32 input via half-length complex FFT (M = 2^25):
//   z[n] = x[2n] + i x[2n+1]  (free reinterpret), Z = FFT_M(z), Hermitian unpack.
//   P1:  radix-256, s=1      z -> D   (d_out as complex scratch)   [verified]
//   P2:  radix-256, s=256    D -> B   (g_buf)                      [verified]
//   P3U: PERSISTENT radix-512 final (s=2^16) fused with unpack.
//        1024 threads (round-8 verified FFT/unpack body), 3 smem slots,
//        cp.async prefetch of pair i+1 overlaps compute of pair i,
//        both halves butterflied in parallel between shared barriers.

#define NFFT  (1u << 26)
#define MFFT  (1u << 25)
#define M256  (1u << 17)   // MFFT / 256
#define S512  (1u << 16)   // MFFT / 512
#define NPAIR 2049u        // (S512/2)/16 pairs + 1 self-mirror chunk
#define NGRID 148u
#define TWO_PI 6.28318530717958647692f
#define INVM  (1.0f / 33554432.0f)
#define INVN  (1.0f / 67108864.0f)
#define GSK   513u                 // group stride in float2 (odd -> conflict-free)
#define HBUF  (16u * GSK)          // one 16-group half-chunk slot

static __device__ float2 g_buf[MFFT];  // 256 MB scratch (sanctioned)

// exp(-2*pi*i*j/256), j = 0..15
__constant__ float2 c_w256[16] = {
    { 1.00000000000000000f, -0.00000000000000000f},
    { 0.99969881869620422f, -0.02454122852291229f},
    { 0.99879545620517241f, -0.04906767432741801f},
    { 0.99729045667869021f, -0.07356456359966743f},
    { 0.99518472667219693f, -0.09801714032956060f},
    { 0.99247953459870997f, -0.12241067519921620f},
    { 0.98917650996478101f, -0.14673047445536175f},
    { 0.98527764238894122f, -0.17096188876030122f},
    { 0.98078528040323044f, -0.19509032201612825f},
    { 0.97570213003852857f, -0.21910124015686980f},
    { 0.97003125319454397f, -0.24298017990326390f},
    { 0.96377606579543984f, -0.26671275747489837f},
    { 0.95694033573220882f, -0.29028467725446233f},
    { 0.94952818059303667f, -0.31368174039889152f},
    { 0.94154406518302081f, -0.33688985339222005f},
    { 0.93299279883473896f, -0.35989503653498817f}
};
// exp(-2*pi*i*k/32), k = 0..15
__constant__ float2 c_w32[16] = {
    { 1.00000000000000000f, -0.00000000000000000f},
    { 0.98078528040323045f, -0.19509032201612827f},
    { 0.92387953251128676f, -0.38268343236508977f},
    { 0.83146961230254524f, -0.55557023301960222f},
    { 0.70710678118654752f, -0.70710678118654752f},
    { 0.55557023301960222f, -0.83146961230254524f},
    { 0.38268343236508977f, -0.92387953251128676f},
    { 0.19509032201612827f, -0.98078528040323045f},
    { 0.00000000000000000f, -1.00000000000000000f},
    {-0.19509032201612827f, -0.98078528040323045f},
    {-0.38268343236508977f, -0.92387953251128676f},
    {-0.55557023301960222f, -0.83146961230254524f},
    {-0.70710678118654752f, -0.70710678118654752f},
    {-0.83146961230254524f, -0.55557023301960222f},
    {-0.92387953251128676f, -0.38268343236508977f},
    {-0.98078528040323045f, -0.19509032201612827f}
};

__device__ __forceinline__ float2 cmul(float2 a, float2 b) {
    return make_float2(a.x * b.x - a.y * b.y, a.x * b.y + a.y * b.x);
}
__device__ __forceinline__ float2 cadd(float2 a, float2 b) {
    return make_float2(a.x + b.x, a.y + b.y);
}
__device__ __forceinline__ float2 csub(float2 a, float2 b) {
    return make_float2(a.x - b.x, a.y - b.y);
}
__device__ __forceinline__ float2 cmul_negi(float2 a) { return make_float2(a.y, -a.x); }
__device__ __forceinline__ float2 cmul_posi(float2 a) { return make_float2(-a.y, a.x); }

// In-place forward DFT-16, natural order in/out (verified rounds 2-10).
__device__ __forceinline__ void dft16(float2 a[16]) {
    const float C1 = 0.92387953251128675613f;
    const float S1 = 0.38268343236508977173f;
    const float H  = 0.70710678118654752440f;
    const float2 W1 = make_float2( C1, -S1);
    const float2 W2 = make_float2(  H,  -H);
    const float2 W3 = make_float2( S1, -C1);
    const float2 W4 = make_float2(0.f, -1.f);
    const float2 W6 = make_float2( -H,  -H);
    const float2 W9 = make_float2(-C1,  S1);
    float2 b[16];
#pragma unroll
    for (int r1 = 0; r1 < 4; ++r1) {
        float2 x0 = a[r1], x1 = a[r1 + 4], x2 = a[r1 + 8], x3 = a[r1 + 12];
        float2 e = cadd(x0, x2), f = csub(x0, x2);
        float2 g = cadd(x1, x3), h = csub(x1, x3);
        b[r1 * 4 + 0] = cadd(e, g);
        b[r1 * 4 + 1] = cadd(f, cmul_negi(h));
        b[r1 * 4 + 2] = csub(e, g);
        b[r1 * 4 + 3] = cadd(f, cmul_posi(h));
    }
    b[5]  = cmul(b[5],  W1);
    b[6]  = cmul(b[6],  W2);
    b[7]  = cmul(b[7],  W3);
    b[9]  = cmul(b[9],  W2);
    b[10] = cmul(b[10], W4);
    b[11] = cmul(b[11], W6);
    b[13] = cmul(b[13], W3);
    b[14] = cmul(b[14], W6);
    b[15] = cmul(b[15], W9);
#pragma unroll
    for (int k1 = 0; k1 < 4; ++k1) {
        float2 x0 = b[k1], x1 = b[4 + k1], x2 = b[8 + k1], x3 = b[12 + k1];
        float2 e = cadd(x0, x2), f = csub(x0, x2);
        float2 g = cadd(x1, x3), h = csub(x1, x3);
        a[k1 + 0]  = cadd(e, g);
        a[k1 + 4]  = cadd(f, cmul_negi(h));
        a[k1 + 8]  = csub(e, g);
        a[k1 + 12] = cadd(f, cmul_posi(h));
    }
}

__device__ __forceinline__ unsigned swz(unsigned l) { return l + (l >> 8); }

// ---------------------------------------------------------------------------
// P1: radix-256, s=1, complex input (verified rounds 7-10).
// ---------------------------------------------------------------------------
__global__ void __launch_bounds__(256) fft256_first(const float2* __restrict__ x,
                                                    float2* __restrict__ y) {
    __shared__ float2 sm[4112];
    unsigned tid = threadIdx.x;
    unsigned g = tid & 15u, j2 = tid >> 4;
    unsigned t = blockIdx.x * 16u + g;

    float2 a[16];
#pragma unroll
    for (int i = 0; i < 16; ++i) a[i] = x[t + (16u * (unsigned)i + j2) * M256];
    dft16(a);

    float sn, cs;
    __sincosf(-TWO_PI * (float)t * INVM, &sn, &cs);
    float2 wg = make_float2(cs, sn);
    float2 w1 = cmul(c_w256[j2], wg);
    float2 w = make_float2(1.f, 0.f);
#pragma unroll
    for (int k1 = 0; k1 < 16; ++k1) {
        sm[swz(tid + 256u * (unsigned)k1)] = cmul(a[k1], w);
        w = cmul(w, w1);
    }
    __syncthreads();

    unsigned k1p = tid >> 4;
#pragma unroll
    for (int j = 0; j < 16; ++j)
        a[j] = sm[swz(256u * k1p + 16u * (unsigned)j + g)];
    dft16(a);

    float2 w2 = cmul(wg, wg);
    w2 = cmul(w2, w2); w2 = cmul(w2, w2); w2 = cmul(w2, w2);  // wg^16
    float2 r[16];
    w = make_float2(1.f, 0.f);
#pragma unroll
    for (int k2 = 0; k2 < 16; ++k2) { r[k2] = cmul(a[k2], w); w = cmul(w, w2); }

    __syncthreads();
#pragma unroll
    for (int k2 = 0; k2 < 16; ++k2)
        sm[swz(256u * g + k1p + 16u * (unsigned)k2)] = r[k2];
    __syncthreads();

    unsigned base = blockIdx.x * 4096u;
#pragma unroll
    for (int i = 0; i < 16; ++i) {
        unsigned m = tid + 256u * (unsigned)i;
        y[base + m] = sm[swz(m)];
    }
}

// ---------------------------------------------------------------------------
// P2: radix-256 mid stage, log2s = 8 (verified rounds 7-10).
// ---------------------------------------------------------------------------
__global__ void __launch_bounds__(256) fft256_mid(const float2* __restrict__ x,
                                                  float2* __restrict__ y,
                                                  int log2s) {
    __shared__ float2 sm[4112];
    unsigned tid = threadIdx.x;
    unsigned g = tid & 15u, j2 = tid >> 4;
    unsigned t = blockIdx.x * 16u + g;
    unsigned s = 1u << log2s;
    unsigned q = t & (s - 1u);
    unsigned ps = t - q;

    float2 a[16];
#pragma unroll
    for (int i = 0; i < 16; ++i) a[i] = x[t + (16u * (unsigned)i + j2) * M256];
    dft16(a);

    float sn, cs;
    __sincosf(-TWO_PI * (float)ps * INVM, &sn, &cs);
    float2 wg = make_float2(cs, sn);
    float2 w1 = cmul(c_w256[j2], wg);
    float2 w = make_float2(1.f, 0.f);
#pragma unroll
    for (int k1 = 0; k1 < 16; ++k1) {
        sm[swz(tid + 256u * (unsigned)k1)] = cmul(a[k1], w);
        w = cmul(w, w1);
    }
    __syncthreads();

    unsigned k1p = tid >> 4;
#pragma unroll
    for (int j = 0; j < 16; ++j)
        a[j] = sm[swz(256u * k1p + 16u * (unsigned)j + g)];
    dft16(a);

    float2 w2 = cmul(wg, wg);
    w2 = cmul(w2, w2); w2 = cmul(w2, w2); w2 = cmul(w2, w2);
    unsigned base = q + (ps << 8) + (k1p << log2s);
    w = make_float2(1.f, 0.f);
#pragma unroll
    for (int k2 = 0; k2 < 16; ++k2) {
        y[base + ((unsigned)k2 << (log2s + 4))] = cmul(a[k2], w);
        w = cmul(w, w2);
    }
}

// ----------------------------- cp.async helpers -----------------------------
__device__ __forceinline__ void cp_async8(void* smem_dst, const void* gmem_src) {
    unsigned d = (unsigned)__cvta_generic_to_shared(smem_dst);
    asm volatile("cp.async.ca.shared.global [%0], [%1], 8;\n" :: "r"(d), "l"(gmem_src));
}
__device__ __forceinline__ void cp_commit() {
    asm volatile("cp.async.commit_group;\n");
}
__device__ __forceinline__ void cp_wait1() {
    asm volatile("cp.async.wait_group 1;\n");
}
__device__ __forceinline__ void cp_wait0() {
    asm volatile("cp.async.wait_group 0;\n");
}

// ---------------------------------------------------------------------------
// P3U v3: persistent, 1024 threads, round-8-verified FFT/unpack body.
// Pair p: half A = groups tA = 16p+g; half B = Hermitian mirrors
// tB = (S512 - 16p - 15 + g) mod S512 (group 15-g mirrors g).
// ---------------------------------------------------------------------------

// Load one 16-group half into slot via cp.async (all 1024 threads).
__device__ __forceinline__ void p3_load_half(const float2* __restrict__ x,
                                             float2* __restrict__ sm,
                                             unsigned slot, unsigned p, int half,
                                             unsigned lg, unsigned lu) {
    unsigned t = half ? ((S512 - 16u * p - 15u + lg) & (S512 - 1u))
                      : (16u * p + lg);
    float2* dst = sm + slot * HBUF + lg * GSK;
#pragma unroll
    for (int j = 0; j < 8; ++j) {
        unsigned r = lu + 64u * (unsigned)j;
        cp_async8(dst + r, x + t + r * S512);
    }
}

__global__ void __launch_bounds__(1024, 1) fft512_unpack_persist(
        const float2* __restrict__ x, float* __restrict__ out) {
    extern __shared__ float2 sm[];
    const unsigned tid = threadIdx.x;
    // load mapping (all threads, one half at a time)
    const unsigned lg = tid & 15u, lu = tid >> 4;        // lu in [0,64)
    // FFT mapping (parallel halves): threads 0-511 -> slot A, 512-1023 -> slot B
    const unsigned fg = tid & 15u;
    const unsigned fu = (tid >> 4) & 31u;
    const unsigned half = tid >> 9;

    unsigned p = blockIdx.x;
    if (p >= NPAIR) return;

    // Prologue: stream both halves of the first pair.
    p3_load_half(x, sm, 0u, p, 0, lg, lu); cp_commit();
    p3_load_half(x, sm, 1u, p, 1, lg, lu); cp_commit();
    unsigned sA = 0u, sB = 1u, sF = 2u;

    for (;;) {
        unsigned pn = p + NGRID;
        bool has_next = (pn < NPAIR);
        if (has_next) { p3_load_half(x, sm, sF, pn, 0, lg, lu); cp_commit(); }

        if (has_next) cp_wait1(); else cp_wait0();
        __syncthreads();  // current pair's halves visible

        // ---- FFT phase: both slots in parallel, shared barriers ----
        {
            float2* gb = sm + (half ? sB : sA) * HBUF + fg * GSK;
            float2 a[16];
            // SA: radix-16, s=1
#pragma unroll
            for (int j = 0; j < 16; ++j) a[j] = gb[fu + 32u * (unsigned)j];
            dft16(a);
            __syncthreads();  // input reads done before in-place overwrite
            {
                float sn, cs;
                __sincosf(-TWO_PI * (float)fu * (1.0f / 512.0f), &sn, &cs);
                float2 wa = make_float2(cs, sn), w = make_float2(1.f, 0.f);
#pragma unroll
                for (int k = 0; k < 16; ++k) {
                    gb[16u * fu + (unsigned)k] = cmul(a[k], w);
                    w = cmul(w, wa);
                }
            }
            __syncthreads();
            // SB: radix-16, s=16
#pragma unroll
            for (int j = 0; j < 16; ++j) a[j] = gb[fu + 32u * (unsigned)j];
            dft16(a);
            __syncthreads();
            {
                unsigned q15 = fu & 15u, p2 = fu >> 4;
#pragma unroll
                for (int k = 0; k < 16; ++k) {
                    float2 v = (p2 == 0u) ? a[k] : cmul(a[k], c_w32[k]);
                    gb[q15 + 256u * p2 + 16u * (unsigned)k] = v;
                }
            }
            __syncthreads();
            // SC: radix-2, s=256, same-thread in-place
#pragma unroll
            for (int i = 0; i < 8; ++i) {
                unsigned t2 = fu + 32u * (unsigned)i;
                float2 b0 = gb[t2];
                float2 b1 = gb[t2 + 256u];
                gb[t2]        = cadd(b0, b1);
                gb[t2 + 256u] = csub(b0, b1);
            }
        }
        __syncthreads();  // SC results visible before cross-group unpack reads

        // ---- unpack phase (round-8 verified; 1024 threads, 8 k's each) ----
        {
            const unsigned gA = tid & 15u;
            const unsigned uu = tid >> 4;          // [0, 64)
            const unsigned t = 16u * p + gA;       // A-group t (< S512)
            const float2* gbA = sm + sA * HBUF + gA * GSK;
            const float2* gbB = sm + sB * HBUF + (15u - gA) * GSK;
            const bool tzero = (t == 0u);

            float sn, cs;
            __sincosf(-TWO_PI * (float)(t + uu * S512) * INVN, &sn, &cs);
            float2 W = make_float2(cs, sn);
            const float2 Winc = c_w32[2];          // e^{-2pi i/16}: k += 64 step

#pragma unroll
            for (int j = 0; j < 8; ++j) {
                unsigned k = uu + 64u * (unsigned)j;
                float2 Zk = gbA[k];
                unsigned kp = tzero ? ((512u - k) & 511u) : (511u - k);
                float2 Zm = gbB[kp];

                float2 A = make_float2(0.5f * (Zk.x + Zm.x), 0.5f * (Zk.y - Zm.y));
                float2 C = make_float2(0.5f * (Zk.x - Zm.x), 0.5f * (Zk.y + Zm.y));
                float2 B = make_float2(C.y, -C.x);
                float2 WB = cmul(W, B);
                float2 P = cadd(A, WB);
                float2 Q = csub(A, WB);

                unsigned m = t + k * S512;               // [0, M)
                unsigned i3 = (NFFT - m) & (NFFT - 1u);  // N - m (mod N)
                unsigned i2 = MFFT - m;
                unsigned i4 = MFFT + m;

                out[m]  = P.x;   out[NFFT + m]  = P.y;
                out[i3] = P.x;   out[NFFT + i3] = -P.y;
                out[i2] = Q.x;   out[NFFT + i2] = -Q.y;
                out[i4] = Q.x;   out[NFFT + i4] = Q.y;

                W = cmul(W, Winc);
            }
        }
        __syncthreads();  // unpack reads done before slot sA is reused

        if (!has_next) break;
        p3_load_half(x, sm, sA, pn, 1, lg, lu); cp_commit();  // B(pn) -> freed sA

        unsigned oldA = sA;
        sA = sF;      // holds A(pn)
        sF = sB;      // free; receives A(pn+NGRID) next iteration
        sB = oldA;    // receiving B(pn)
        p = pn;
    }
}

// ---------------------------------------------------------------------------
// Schedule: P1: z -> D (d_out scratch); P2: D -> B (g_buf); P3U: B -> out.
// P3U reads only g_buf, writes only d_out: no aliasing hazard.
// ---------------------------------------------------------------------------
extern "C" void kernel_launch(void* const* d_in, const int* in_sizes, int n_in,
                              void* d_out, int out_size) {
    const float2* z = (const float2*)d_in[0];   // N reals = M complex (free pack)
    float* out = (float*)d_out;
    float2* D = (float2*)d_out;                 // M float2 scratch fits in out
    float2* B = nullptr;
    cudaGetSymbolAddress((void**)&B, g_buf);

    const size_t smem3 = (size_t)(3u * HBUF) * sizeof(float2);  // 196,992 B
    cudaFuncSetAttribute(fft512_unpack_persist,
                         cudaFuncAttributeMaxDynamicSharedMemorySize, (int)smem3);

    fft256_first <<<M256 / 16u, 256>>>(z, D);            // 8192 blocks
    fft256_mid   <<<M256 / 16u, 256>>>(D, B, 8);         // 8192 blocks
    fft512_unpack_persist<<<NGRID, 1024, smem3>>>(B, out);
}

// round 12
// speedup vs baseline: 1.0496x; 1.0496x over previous
#include <cuda_runtime.h>

// N = 2^26 FFT of REAL fp32 input via half-length complex FFT (M = 2^25):
//   z[n] = x[2n] + i x[2n+1] (free reinterpret), Z = FFT_M(z), Hermitian unpack.
// Decomposition M = 256 * 512 * 256:
//   P1:  radix-256, s=1      z -> D   (d_out scratch)        [verified body]
//   P2:  radix-512, s=256    D -> B   (g_buf)                [verified FFT body]
//   P3U: radix-256 FINAL (s=2^17, ps=0 => twiddle-free) fused with unpack.
//        512 thr = 2 x 256 (A half + Hermitian-mirror B half), 66KB smem,
//        2 blocks/SM. B -> planar out.

#define NFFT  (1u << 26)
#define MFFT  (1u << 25)
#define M256  (1u << 17)   // MFFT/256: pass1 group count & pass3 load stride base
#define M512  (1u << 16)   // MFFT/512: pass2 group count & pass2 load stride
#define SFIN  (1u << 17)   // final-pass stride s
#define NPAIR3 4097u
#define TWO_PI 6.28318530717958647692f
#define INVM  (1.0f / 33554432.0f)
#define INVN  (1.0f / 67108864.0f)

static __device__ float2 g_buf[MFFT];  // 256 MB scratch (sanctioned)

// exp(-2*pi*i*j/256), j = 0..15
__constant__ float2 c_w256[16] = {
    { 1.00000000000000000f, -0.00000000000000000f},
    { 0.99969881869620422f, -0.02454122852291229f},
    { 0.99879545620517241f, -0.04906767432741801f},
    { 0.99729045667869021f, -0.07356456359966743f},
    { 0.99518472667219693f, -0.09801714032956060f},
    { 0.99247953459870997f, -0.12241067519921620f},
    { 0.98917650996478101f, -0.14673047445536175f},
    { 0.98527764238894122f, -0.17096188876030122f},
    { 0.98078528040323044f, -0.19509032201612825f},
    { 0.97570213003852857f, -0.21910124015686980f},
    { 0.97003125319454397f, -0.24298017990326390f},
    { 0.96377606579543984f, -0.26671275747489837f},
    { 0.95694033573220882f, -0.29028467725446233f},
    { 0.94952818059303667f, -0.31368174039889152f},
    { 0.94154406518302081f, -0.33688985339222005f},
    { 0.93299279883473896f, -0.35989503653498817f}
};
// exp(-2*pi*i*k/32), k = 0..15
__constant__ float2 c_w32[16] = {
    { 1.00000000000000000f, -0.00000000000000000f},
    { 0.98078528040323045f, -0.19509032201612827f},
    { 0.92387953251128676f, -0.38268343236508977f},
    { 0.83146961230254524f, -0.55557023301960222f},
    { 0.70710678118654752f, -0.70710678118654752f},
    { 0.55557023301960222f, -0.83146961230254524f},
    { 0.38268343236508977f, -0.92387953251128676f},
    { 0.19509032201612827f, -0.98078528040323045f},
    { 0.00000000000000000f, -1.00000000000000000f},
    {-0.19509032201612827f, -0.98078528040323045f},
    {-0.38268343236508977f, -0.92387953251128676f},
    {-0.55557023301960222f, -0.83146961230254524f},
    {-0.70710678118654752f, -0.70710678118654752f},
    {-0.83146961230254524f, -0.55557023301960222f},
    {-0.92387953251128676f, -0.38268343236508977f},
    {-0.98078528040323045f, -0.19509032201612827f}
};

__device__ __forceinline__ float2 cmul(float2 a, float2 b) {
    return make_float2(a.x * b.x - a.y * b.y, a.x * b.y + a.y * b.x);
}
__device__ __forceinline__ float2 cadd(float2 a, float2 b) {
    return make_float2(a.x + b.x, a.y + b.y);
}
__device__ __forceinline__ float2 csub(float2 a, float2 b) {
    return make_float2(a.x - b.x, a.y - b.y);
}
__device__ __forceinline__ float2 cmul_negi(float2 a) { return make_float2(a.y, -a.x); }
__device__ __forceinline__ float2 cmul_posi(float2 a) { return make_float2(-a.y, a.x); }

// In-place forward DFT-16, natural order in/out (verified rounds 2-11).
__device__ __forceinline__ void dft16(float2 a[16]) {
    const float C1 = 0.92387953251128675613f;
    const float S1 = 0.38268343236508977173f;
    const float H  = 0.70710678118654752440f;
    const float2 W1 = make_float2( C1, -S1);
    const float2 W2 = make_float2(  H,  -H);
    const float2 W3 = make_float2( S1, -C1);
    const float2 W4 = make_float2(0.f, -1.f);
    const float2 W6 = make_float2( -H,  -H);
    const float2 W9 = make_float2(-C1,  S1);
    float2 b[16];
#pragma unroll
    for (int r1 = 0; r1 < 4; ++r1) {
        float2 x0 = a[r1], x1 = a[r1 + 4], x2 = a[r1 + 8], x3 = a[r1 + 12];
        float2 e = cadd(x0, x2), f = csub(x0, x2);
        float2 g = cadd(x1, x3), h = csub(x1, x3);
        b[r1 * 4 + 0] = cadd(e, g);
        b[r1 * 4 + 1] = cadd(f, cmul_negi(h));
        b[r1 * 4 + 2] = csub(e, g);
        b[r1 * 4 + 3] = cadd(f, cmul_posi(h));
    }
    b[5]  = cmul(b[5],  W1);
    b[6]  = cmul(b[6],  W2);
    b[7]  = cmul(b[7],  W3);
    b[9]  = cmul(b[9],  W2);
    b[10] = cmul(b[10], W4);
    b[11] = cmul(b[11], W6);
    b[13] = cmul(b[13], W3);
    b[14] = cmul(b[14], W6);
    b[15] = cmul(b[15], W9);
#pragma unroll
    for (int k1 = 0; k1 < 4; ++k1) {
        float2 x0 = b[k1], x1 = b[4 + k1], x2 = b[8 + k1], x3 = b[12 + k1];
        float2 e = cadd(x0, x2), f = csub(x0, x2);
        float2 g = cadd(x1, x3), h = csub(x1, x3);
        a[k1 + 0]  = cadd(e, g);
        a[k1 + 4]  = cadd(f, cmul_negi(h));
        a[k1 + 8]  = csub(e, g);
        a[k1 + 12] = cadd(f, cmul_posi(h));
    }
}

__device__ __forceinline__ unsigned swz(unsigned l) { return l + (l >> 8); }

// ---------------------------------------------------------------------------
// P1: radix-256, s=1, complex input (verified rounds 7-11, verbatim).
// ---------------------------------------------------------------------------
__global__ void __launch_bounds__(256) fft256_first(const float2* __restrict__ x,
                                                    float2* __restrict__ y) {
    __shared__ float2 sm[4112];
    unsigned tid = threadIdx.x;
    unsigned g = tid & 15u, j2 = tid >> 4;
    unsigned t = blockIdx.x * 16u + g;

    float2 a[16];
#pragma unroll
    for (int i = 0; i < 16; ++i) a[i] = x[t + (16u * (unsigned)i + j2) * M256];
    dft16(a);

    float sn, cs;
    __sincosf(-TWO_PI * (float)t * INVM, &sn, &cs);
    float2 wg = make_float2(cs, sn);
    float2 w1 = cmul(c_w256[j2], wg);
    float2 w = make_float2(1.f, 0.f);
#pragma unroll
    for (int k1 = 0; k1 < 16; ++k1) {
        sm[swz(tid + 256u * (unsigned)k1)] = cmul(a[k1], w);
        w = cmul(w, w1);
    }
    __syncthreads();

    unsigned k1p = tid >> 4;
#pragma unroll
    for (int j = 0; j < 16; ++j)
        a[j] = sm[swz(256u * k1p + 16u * (unsigned)j + g)];
    dft16(a);

    float2 w2 = cmul(wg, wg);
    w2 = cmul(w2, w2); w2 = cmul(w2, w2); w2 = cmul(w2, w2);  // wg^16
    float2 r[16];
    w = make_float2(1.f, 0.f);
#pragma unroll
    for (int k2 = 0; k2 < 16; ++k2) { r[k2] = cmul(a[k2], w); w = cmul(w, w2); }

    __syncthreads();
#pragma unroll
    for (int k2 = 0; k2 < 16; ++k2)
        sm[swz(256u * g + k1p + 16u * (unsigned)k2)] = r[k2];
    __syncthreads();

    unsigned base = blockIdx.x * 4096u;
#pragma unroll
    for (int i = 0; i < 16; ++i) {
        unsigned m = tid + 256u * (unsigned)i;
        y[base + m] = sm[swz(m)];
    }
}

// ---------------------------------------------------------------------------
// P2: radix-512 mid stage, s=256. FFT body = round-7 verified fft512_last
// (same group count 2^16, same load stride 2^16); epilogue adds the mid-stage
// twiddle W^k (W = e^{-2pi i ps/M}) and scatter y[q + 512 s p + k s].
// ---------------------------------------------------------------------------
#define GS3 513u
__global__ void __launch_bounds__(512) fft512_mid(const float2* __restrict__ x,
                                                  float2* __restrict__ y) {
    extern __shared__ float2 sm[];
    const unsigned tid = threadIdx.x;
    const unsigned g = tid & 15u, u = tid >> 4;   // u in [0,32)
    const unsigned t = blockIdx.x * 16u + g;      // t in [0, 2^16)
    const unsigned gb = g * GS3;

    float2 a[16];
#pragma unroll
    for (int j = 0; j < 16; ++j) a[j] = x[t + (u + 32u * (unsigned)j) * M512];

    // SA: radix-16, s=1
    dft16(a);
    {
        float sn, cs;
        __sincosf(-TWO_PI * (float)u * (1.0f / 512.0f), &sn, &cs);
        float2 wa = make_float2(cs, sn), w = make_float2(1.f, 0.f);
#pragma unroll
        for (int k = 0; k < 16; ++k) {
            sm[gb + 16u * u + (unsigned)k] = cmul(a[k], w);
            w = cmul(w, wa);
        }
    }
    __syncthreads();

    // SB: radix-16, s=16
#pragma unroll
    for (int j = 0; j < 16; ++j) a[j] = sm[gb + u + 32u * (unsigned)j];
    dft16(a);
    __syncthreads();
    {
        unsigned q15 = u & 15u, p = u >> 4;  // p in {0,1}
#pragma unroll
        for (int k = 0; k < 16; ++k) {
            float2 v = (p == 0u) ? a[k] : cmul(a[k], c_w32[k]);
            sm[gb + q15 + 256u * p + 16u * (unsigned)k] = v;
        }
    }
    __syncthreads();

    // SC: radix-2, s=256 + mid-stage twiddle + scatter.
    const unsigned q = t & 255u;
    const unsigned ps = t - q;
    const float fps = (float)ps;
    float2 Wu, W32, W256;
    { float sn, cs; __sincosf(-TWO_PI * (fps * (float)u) * INVM, &sn, &cs); Wu   = make_float2(cs, sn); }
    { float sn, cs; __sincosf(-TWO_PI * (fps * 32.0f) * INVM, &sn, &cs);    W32  = make_float2(cs, sn); }
    { float sn, cs; __sincosf(-TWO_PI * (fps * 256.0f) * INVM, &sn, &cs);   W256 = make_float2(cs, sn); }

    const unsigned base = q + (ps << 9);
    float2 w = Wu;
#pragma unroll
    for (int i = 0; i < 8; ++i) {
        unsigned t2 = u + 32u * (unsigned)i;
        float2 b0 = sm[gb + t2];
        float2 b1 = sm[gb + t2 + 256u];
        float2 v0 = cadd(b0, b1);   // k = t2
        float2 v1 = csub(b0, b1);   // k = t2 + 256
        y[base + (t2 << 8)]           = cmul(v0, w);
        y[base + ((t2 + 256u) << 8)]  = cmul(v1, cmul(w, W256));
        w = cmul(w, W32);
    }
}

// ---------------------------------------------------------------------------
// P3U: FINAL radix-256 (s=2^17 => ps=0, outer twiddles = 1) fused with
// Hermitian unpack. 512 threads = 2 halves x 256; half A computes chunk
// tA = 16b+g, half B its mirrors tB = (2^17 - 16b - 15 + g) mod 2^17
// (group 15-g mirrors g; t=0 self-mirrors with k' = (256-k) mod 256).
// FFT body = verified fft256_mid with wg=1; Z re-laid to sm[g*257 + k].
// Unpack (r8-verified algebra): A=(Zk+conj Zm)/2, B=-i(Zk-conj Zm)/2,
// W=e^{-2pi i m/N}, P=A+WB->X[m], conj P->X[N-m], Q=A-WB->X[M+m],
// conj Q->X[M-m]. Grid 4097; boundary duplicates are identical writes.
// ---------------------------------------------------------------------------
#define HB3 4128u
__global__ void __launch_bounds__(512) fft256_unpack(const float2* __restrict__ x,
                                                     float* __restrict__ out) {
    extern __shared__ float2 sm[];
    const unsigned tid = threadIdx.x;
    const unsigned bb = blockIdx.x;
    const unsigned half = tid >> 8;
    const unsigned ltid = tid & 255u;
    const unsigned g = ltid & 15u, j2 = ltid >> 4;
    const unsigned tA = 16u * bb + g;
    const unsigned tB = (SFIN - 16u * bb - 15u + g) & (SFIN - 1u);
    const unsigned t = half ? tB : tA;
    const unsigned hb = half * HB3;

    // ---- FFT phase: verified fft256 body, ps=0 (w2=1) ----
    float2 a[16];
#pragma unroll
    for (int i = 0; i < 16; ++i) a[i] = x[t + (16u * (unsigned)i + j2) * SFIN];
    dft16(a);
    {
        float2 w1 = c_w256[j2], w = make_float2(1.f, 0.f);
#pragma unroll
        for (int k1 = 0; k1 < 16; ++k1) {
            sm[hb + swz(ltid + 256u * (unsigned)k1)] = cmul(a[k1], w);
            w = cmul(w, w1);
        }
    }
    __syncthreads();

    const unsigned k1p = ltid >> 4;
#pragma unroll
    for (int j = 0; j < 16; ++j)
        a[j] = sm[hb + swz(256u * k1p + 16u * (unsigned)j + g)];
    dft16(a);
    __syncthreads();  // all staging reads done before Z overwrite

    // Z layout: sm[hb + g*257 + k], k = k1p + 16*k2 (conflict-free: addr%16 = g+k1p)
#pragma unroll
    for (int k2 = 0; k2 < 16; ++k2)
        sm[hb + g * 257u + k1p + 16u * (unsigned)k2] = a[k2];
    __syncthreads();

    // ---- unpack phase (512 threads, 8 k's each) ----
    {
        const unsigned gA = tid & 15u;
        const unsigned uu = tid >> 4;            // [0, 32)
        const unsigned t3 = 16u * bb + gA;       // A-group t (< 2^17)
        const float2* gbA = sm + gA * 257u;
        const float2* gbB = sm + HB3 + (15u - gA) * 257u;
        const bool tzero = (t3 == 0u);

        float sn, cs;
        __sincosf(-TWO_PI * (float)(t3 + uu * SFIN) * INVN, &sn, &cs);
        float2 W = make_float2(cs, sn);
        const float2 Winc = c_w32[2];            // e^{-2pi i/16}: k += 32 step

#pragma unroll
        for (int j = 0; j < 8; ++j) {
            unsigned k = uu + 32u * (unsigned)j;
            float2 Zk = gbA[k];
            unsigned kp = tzero ? ((256u - k) & 255u) : (255u - k);
            float2 Zm = gbB[kp];

            float2 A = make_float2(0.5f * (Zk.x + Zm.x), 0.5f * (Zk.y - Zm.y));
            float2 C = make_float2(0.5f * (Zk.x - Zm.x), 0.5f * (Zk.y + Zm.y));
            float2 B = make_float2(C.y, -C.x);
            float2 WB = cmul(W, B);
            float2 P = cadd(A, WB);
            float2 Q = csub(A, WB);

            unsigned m = t3 + k * SFIN;              // [0, M)
            unsigned i3 = (NFFT - m) & (NFFT - 1u);  // N - m (mod N)
            unsigned i2 = MFFT - m;
            unsigned i4 = MFFT + m;

            out[m]  = P.x;   out[NFFT + m]  = P.y;
            out[i3] = P.x;   out[NFFT + i3] = -P.y;
            out[i2] = Q.x;   out[NFFT + i2] = -Q.y;
            out[i4] = Q.x;   out[NFFT + i4] = Q.y;

            W = cmul(W, Winc);
        }
    }
}

// ---------------------------------------------------------------------------
// Schedule: P1: z -> D (d_out scratch); P2: D -> B (g_buf); P3U: B -> out.
// P3U reads only g_buf, writes only d_out: no aliasing hazard.
// ---------------------------------------------------------------------------
extern "C" void kernel_launch(void* const* d_in, const int* in_sizes, int n_in,
                              void* d_out, int out_size) {
    const float2* z = (const float2*)d_in[0];   // N reals = M complex (free pack)
    float* out = (float*)d_out;
    float2* D = (float2*)d_out;                 // M float2 scratch fits in out
    float2* B = nullptr;
    cudaGetSymbolAddress((void**)&B, g_buf);

    const size_t smem2 = (size_t)(16u * GS3) * sizeof(float2);  // 65,664 B
    const size_t smem3 = (size_t)(2u * HB3) * sizeof(float2);   // 66,048 B
    cudaFuncSetAttribute(fft512_mid,
                         cudaFuncAttributeMaxDynamicSharedMemorySize, (int)smem2);
    cudaFuncSetAttribute(fft256_unpack,
                         cudaFuncAttributeMaxDynamicSharedMemorySize, (int)smem3);

    fft256_first <<<M256 / 16u, 256>>>(z, D);            // 8192 blocks
    fft512_mid   <<<M512 / 16u, 512, smem2>>>(D, B);     // 4096 blocks
    fft256_unpack<<<NPAIR3, 512, smem3>>>(B, out);       // 4097 blocks
}